// round 6
// baseline (speedup 1.0000x reference)
#include <cuda_runtime.h>
#include <math.h>

// MaskedHeteroGAT — exact algebraic reduction.
//
// Layer-2 GATv2 uses x_src = zeros, so its message (alpha * xl[src]) is
// identically zero and h2[t] = b2[t] broadcast to all rows. Therefore:
//   s[t] rows  == p_t = softmax(b2[t] @ Ws[t])        (one [C] vector)
//   s_pkg rows == 1/C exactly
//   cross_t = E_t * (sum_c p_t[c]) / C                (edge indices irrelevant)
//   sq_t    = (N^2 / C) * ||p_t||^2
//   link_t  = sqrt(max(E_t - 2*cross_t + sq_t, 0)) / N^2
//   ent     = ( sum_t H(p_t) + H_uniform ) / 7,  H(p) = -sum p*log(p+1e-15)
//   out     = sum_t link_t + ent
//
// Layer 1 (all GEMMs, gathers, segment softmaxes) is dead code.

__device__ __forceinline__ float warp_max(float v) {
    #pragma unroll
    for (int o = 16; o > 0; o >>= 1)
        v = fmaxf(v, __shfl_xor_sync(0xFFFFFFFFu, v, o));
    return v;
}
__device__ __forceinline__ float warp_sum(float v) {
    #pragma unroll
    for (int o = 16; o > 0; o >>= 1)
        v += __shfl_xor_sync(0xFFFFFFFFu, v, o);
    return v;
}
__device__ __forceinline__ double warp_sum_d(double v) {
    #pragma unroll
    for (int o = 16; o > 0; o >>= 1)
        v += __shfl_xor_sync(0xFFFFFFFFu, v, o);
    return v;
}

__global__ void masked_hetero_gat_scalar_kernel(
    const float* __restrict__ b2,   // [6, HD]
    const float* __restrict__ Ws,   // [6, HD, C]
    float* __restrict__ out,        // [1]
    int HD, int C, double Nnodes,
    long long e0, long long e1, long long e2,
    long long e3, long long e4, long long e5)
{
    extern __shared__ float sh[];          // [6*C] logits
    __shared__ double link_sh[6];
    __shared__ double ent_sh[6];

    const int tid   = threadIdx.x;
    const int total = 6 * C;

    // Stage 1: logits[t][c] = dot(b2[t,:], Ws[t,:,c])  (coalesced over c)
    for (int idx = tid; idx < total; idx += blockDim.x) {
        int t = idx / C;
        int c = idx % C;
        const float* b = b2 + (size_t)t * HD;
        const float* w = Ws + (size_t)t * HD * C + c;
        float acc = 0.0f;
        #pragma unroll 4
        for (int k = 0; k < HD; k++)
            acc = fmaf(b[k], w[(size_t)k * C], acc);
        sh[idx] = acc;
    }
    __syncthreads();

    // Stage 2: one warp per edge type — softmax over C + scalar formulas.
    const int wid  = tid >> 5;
    const int lane = tid & 31;
    if (wid < 6) {
        const int t = wid;
        const float* lg = sh + t * C;

        float m = -INFINITY;
        for (int c = lane; c < C; c += 32) m = fmaxf(m, lg[c]);
        m = warp_max(m);

        float esum = 0.0f;
        for (int c = lane; c < C; c += 32) esum += expf(lg[c] - m);
        esum = warp_sum(esum);

        double sump = 0.0, sumsq = 0.0, H = 0.0;
        for (int c = lane; c < C; c += 32) {
            float p = expf(lg[c] - m) / esum;
            sump  += (double)p;
            sumsq += (double)p * (double)p;
            H     -= (double)(p * logf(p + 1e-15f));
        }
        sump  = warp_sum_d(sump);
        sumsq = warp_sum_d(sumsq);
        H     = warp_sum_d(H);

        if (lane == 0) {
            const long long nes[6] = {e0, e1, e2, e3, e4, e5};
            double ne    = (double)nes[t];
            double cross = ne * sump / (double)C;
            double sq    = (Nnodes * Nnodes / (double)C) * sumsq;
            double v     = ne - 2.0 * cross + sq;
            if (v < 0.0) v = 0.0;
            link_sh[t] = sqrt(v) / (Nnodes * Nnodes);
            ent_sh[t]  = H;
        }
    }
    __syncthreads();

    // Stage 3: combine.
    if (tid == 0) {
        double link = 0.0, entsum = 0.0;
        for (int t = 0; t < 6; t++) {
            link   += link_sh[t];
            entsum += ent_sh[t];
        }
        float invC = 1.0f / (float)C;
        double Hu = -(double)C * (double)(invC * logf(invC + 1e-15f));
        double ent = (entsum + Hu) / 7.0;
        out[0] = (float)(link + ent);
    }
}

extern "C" void kernel_launch(void* const* d_in, const int* in_sizes, int n_in,
                              void* d_out, int out_size)
{
    // Input order (metadata):
    //  0..6  : x_pkg, x_path, x_dns, x_cmd, x_ip, x_port, x_host  [N, F_IN] f32
    //  7..12 : ei_path..ei_host  [2, E_t] i32
    //  13..16: Wl1 [6,F_IN,HD], Wr1 [6,F_IN,HD], a1 [6,H,D], b1 [6,HD]
    //  17..20: Wl2 [6,HD,HD],   Wr2 [6,HD,HD],   a2 [6,H,D], b2 [6,HD]
    //  21    : Ws [6,HD,C]
    (void)n_in; (void)out_size;

    const int HD   = in_sizes[20] / 6;             // b2 = [6, HD]
    const int C    = in_sizes[21] / (6 * HD);      // Ws = [6, HD, C]
    const int F_IN = in_sizes[13] / (6 * HD);      // Wl1 = [6, F_IN, HD]
    const double Nnodes = (double)(in_sizes[0] / F_IN);

    long long ne[6];
    for (int t = 0; t < 6; t++) ne[t] = (long long)(in_sizes[7 + t] / 2);

    const float* b2 = (const float*)d_in[20];
    const float* Ws = (const float*)d_in[21];
    float* out = (float*)d_out;

    int total = 6 * C;
    int block = total < 1024 ? ((total + 31) / 32) * 32 : 1024;
    if (block < 192) block = 192;                  // >= 6 warps for stage 2
    size_t smem = (size_t)total * sizeof(float);

    masked_hetero_gat_scalar_kernel<<<1, block, smem>>>(
        b2, Ws, out, HD, C, Nnodes,
        ne[0], ne[1], ne[2], ne[3], ne[4], ne[5]);
}

// round 7
// speedup vs baseline: 1.3848x; 1.3848x over previous
#include <cuda_runtime.h>
#include <math.h>

// MaskedHeteroGAT — exact algebraic reduction (rel_err = 0.0 measured R6).
//
// Layer-2 GATv2 uses x_src = zeros -> messages are identically zero ->
// h2[t] = b2[t] broadcast. Output collapses to:
//   p_t    = softmax(b2[t] @ Ws[t])                      (six [C] vectors)
//   link_t = sqrt(max(E_t - 2*E_t*sum(p_t)/C + (N^2/C)*||p_t||^2, 0)) / N^2
//   ent    = ( sum_t H(p_t) + H_uniform ) / 7
//   out    = sum_t link_t + ent
//
// R6 ncu: latency-bound, single SM, issue 5.6%. This version: k-split x2 +
// float2 column pairs + 8 loads in flight -> ~4x fewer serial mem round trips.

__device__ __forceinline__ float warp_max(float v) {
    #pragma unroll
    for (int o = 16; o > 0; o >>= 1)
        v = fmaxf(v, __shfl_xor_sync(0xFFFFFFFFu, v, o));
    return v;
}
__device__ __forceinline__ float warp_sum(float v) {
    #pragma unroll
    for (int o = 16; o > 0; o >>= 1)
        v += __shfl_xor_sync(0xFFFFFFFFu, v, o);
    return v;
}
__device__ __forceinline__ double warp_sum_d(double v) {
    #pragma unroll
    for (int o = 16; o > 0; o >>= 1)
        v += __shfl_xor_sync(0xFFFFFFFFu, v, o);
    return v;
}

__global__ void masked_hetero_gat_scalar_kernel(
    const float* __restrict__ b2,   // [6, HD]
    const float* __restrict__ Ws,   // [6, HD, C]
    float* __restrict__ out,        // [1]
    int HD, int C, double Nnodes,
    long long e0, long long e1, long long e2,
    long long e3, long long e4, long long e5)
{
    extern __shared__ float sh[];
    float* b2s  = sh;               // [6*HD]
    float* part = sh + 6 * HD;      // [6*C*2] k-split partial logits
    __shared__ double link_sh[6];
    __shared__ double ent_sh[6];

    const int tid = threadIdx.x;
    const int nb  = blockDim.x;

    // Stage 0: stage b2 into shared (broadcast reuse by 2*C threads per type).
    for (int i = tid; i < 6 * HD; i += nb) b2s[i] = b2[i];
    __syncthreads();

    // Stage 1: partial logits. Fast path: even C and HD -> float2 column
    // pairs + k-split by 2 + 8 loads in flight.
    if (((C | HD) & 1) == 0) {
        const int cp     = C >> 1;      // column pairs
        const int halfHD = HD >> 1;
        const int work   = 6 * cp * 2;  // (t, cpair, khalf)
        for (int w = tid; w < work; w += nb) {
            const int h     = w & 1;
            const int q     = w >> 1;
            const int t     = q / cp;
            const int cpair = q % cp;
            const int c0    = cpair * 2;

            const float*  b  = b2s + t * HD + h * halfHD;
            const float2* wp = (const float2*)(Ws + (size_t)t * HD * C
                                                  + (size_t)h * halfHD * C + c0);
            const int s2 = C >> 1;      // float2 stride per k step

            float a0 = 0.f, a1 = 0.f, d0 = 0.f, d1 = 0.f;
            int k = 0;
            #pragma unroll 4
            for (; k + 1 < halfHD; k += 2) {
                float2 w0 = wp[(size_t)k * s2];
                float2 w1 = wp[(size_t)(k + 1) * s2];
                float bk0 = b[k], bk1 = b[k + 1];
                a0 = fmaf(bk0, w0.x, a0);
                a1 = fmaf(bk0, w0.y, a1);
                d0 = fmaf(bk1, w1.x, d0);
                d1 = fmaf(bk1, w1.y, d1);
            }
            for (; k < halfHD; k++) {
                float2 w0 = wp[(size_t)k * s2];
                a0 = fmaf(b[k], w0.x, a0);
                a1 = fmaf(b[k], w0.y, a1);
            }
            part[(t * C + c0)     * 2 + h] = a0 + d0;
            part[(t * C + c0 + 1) * 2 + h] = a1 + d1;
        }
    } else {
        // Scalar fallback (odd shapes): one thread per (t, c), no k-split.
        const int total = 6 * C;
        for (int idx = tid; idx < total; idx += nb) {
            int t = idx / C;
            int c = idx % C;
            const float* b = b2s + t * HD;
            const float* w = Ws + (size_t)t * HD * C + c;
            float acc = 0.0f;
            #pragma unroll 4
            for (int k = 0; k < HD; k++)
                acc = fmaf(b[k], w[(size_t)k * C], acc);
            part[idx * 2]     = acc;
            part[idx * 2 + 1] = 0.0f;
        }
    }
    __syncthreads();

    // Stage 2: one warp per edge type — softmax over C + scalar formulas.
    const int wid  = tid >> 5;
    const int lane = tid & 31;
    if (wid < 6) {
        const int t = wid;
        const float* pt = part + t * C * 2;

        float m = -INFINITY;
        for (int c = lane; c < C; c += 32)
            m = fmaxf(m, pt[c * 2] + pt[c * 2 + 1]);
        m = warp_max(m);

        float esum = 0.0f;
        for (int c = lane; c < C; c += 32)
            esum += expf(pt[c * 2] + pt[c * 2 + 1] - m);
        esum = warp_sum(esum);

        double sump = 0.0, sumsq = 0.0, H = 0.0;
        for (int c = lane; c < C; c += 32) {
            float p = expf(pt[c * 2] + pt[c * 2 + 1] - m) / esum;
            sump  += (double)p;
            sumsq += (double)p * (double)p;
            H     -= (double)(p * logf(p + 1e-15f));
        }
        sump  = warp_sum_d(sump);
        sumsq = warp_sum_d(sumsq);
        H     = warp_sum_d(H);

        if (lane == 0) {
            const long long nes[6] = {e0, e1, e2, e3, e4, e5};
            double ne    = (double)nes[t];
            double cross = ne * sump / (double)C;
            double sq    = (Nnodes * Nnodes / (double)C) * sumsq;
            double v     = ne - 2.0 * cross + sq;
            if (v < 0.0) v = 0.0;
            link_sh[t] = sqrt(v) / (Nnodes * Nnodes);
            ent_sh[t]  = H;
        }
    }
    __syncthreads();

    // Stage 3: combine.
    if (tid == 0) {
        double link = 0.0, entsum = 0.0;
        for (int t = 0; t < 6; t++) {
            link   += link_sh[t];
            entsum += ent_sh[t];
        }
        float invC = 1.0f / (float)C;
        double Hu = -(double)C * (double)(invC * logf(invC + 1e-15f));
        double ent = (entsum + Hu) / 7.0;
        out[0] = (float)(link + ent);
    }
}

extern "C" void kernel_launch(void* const* d_in, const int* in_sizes, int n_in,
                              void* d_out, int out_size)
{
    // Input order (metadata):
    //  0..6  : node features [N, F_IN] f32
    //  7..12 : ei_path..ei_host  [2, E_t] i32
    //  13..16: Wl1 [6,F_IN,HD], Wr1, a1, b1 [6,HD]
    //  17..20: Wl2 [6,HD,HD],   Wr2, a2, b2 [6,HD]
    //  21    : Ws [6,HD,C]
    (void)n_in; (void)out_size;

    const int HD   = in_sizes[20] / 6;             // b2 = [6, HD]
    const int C    = in_sizes[21] / (6 * HD);      // Ws = [6, HD, C]
    const int F_IN = in_sizes[13] / (6 * HD);      // Wl1 = [6, F_IN, HD]
    const double Nnodes = (double)(in_sizes[0] / F_IN);

    long long ne[6];
    for (int t = 0; t < 6; t++) ne[t] = (long long)(in_sizes[7 + t] / 2);

    const float* b2 = (const float*)d_in[20];
    const float* Ws = (const float*)d_in[21];
    float* out = (float*)d_out;

    // Fast path work = 6*C threads; fallback work = 6*C. >=192 for 6 warps.
    int work  = 6 * C;
    int block = ((work + 31) / 32) * 32;
    if (block < 192)  block = 192;
    if (block > 1024) block = 1024;
    size_t smem = (size_t)(6 * HD + 6 * C * 2) * sizeof(float);

    masked_hetero_gat_scalar_kernel<<<1, block, smem>>>(
        b2, Ws, out, HD, C, Nnodes,
        ne[0], ne[1], ne[2], ne[3], ne[4], ne[5]);
}